// round 2
// baseline (speedup 1.0000x reference)
#include <cuda_runtime.h>
#include <cuda_bf16.h>

// Problem constants (fixed by setup_inputs)
#define SS 2000   // filtration points
#define PP 2500   // sample points
#define RR 5      // bars per point
#define NB 256    // buckets for counting sort

// Output layout (flattened concatenation, floats):
//   bars_stack : [0, 25000)
//   gm0        : [25000, 50025000)           (R,P,2S)
//   gc0        : [50025000, 50050000)        (R,P,2)
//   gm1        : [50050000, 100050000)
//   gc1        : [100050000, 100075000)

// Bucket-sorted filtration tables (built once per launch by bin_kernel)
__device__ float g_kx[SS], g_cx[SS];   // sorted-by-fx : key=fx, companion=fy
__device__ int   g_sx[SS];
__device__ float g_ky[SS], g_cy[SS];   // sorted-by-fy : key=fy, companion=fx
__device__ int   g_sy[SS];
__device__ int   g_ofx[NB + 1], g_ofy[NB + 1];

__global__ void bin_kernel(const float* __restrict__ filt)
{
    __shared__ int hist[NB];
    __shared__ int off[NB + 1];
    __shared__ int cur[NB];
    int t = threadIdx.x;

    for (int axis = 0; axis < 2; ++axis) {
        if (t < NB) hist[t] = 0;
        __syncthreads();
        for (int s = t; s < SS; s += blockDim.x) {
            float v = filt[2 * s + axis];
            int b = min(NB - 1, max(0, (int)floorf(v * (float)NB)));
            atomicAdd(&hist[b], 1);
        }
        __syncthreads();
        if (t == 0) {
            int acc = 0;
            for (int i = 0; i < NB; ++i) { off[i] = acc; acc += hist[i]; }
            off[NB] = acc;
        }
        __syncthreads();
        for (int i = t; i < NB + 1; i += blockDim.x)
            (axis ? g_ofy : g_ofx)[i] = off[i];
        if (t < NB) cur[t] = off[t];
        __syncthreads();
        for (int s = t; s < SS; s += blockDim.x) {
            float v = filt[2 * s + axis];
            float w = filt[2 * s + (1 - axis)];
            int b = min(NB - 1, max(0, (int)floorf(v * (float)NB)));
            int pos = atomicAdd(&cur[b], 1);
            if (axis == 0) { g_kx[pos] = v; g_cx[pos] = w; g_sx[pos] = s; }
            else           { g_ky[pos] = v; g_cy[pos] = w; g_sy[pos] = s; }
        }
        __syncthreads();
    }
}

__global__ __launch_bounds__(256) void grad_kernel(
    const float* __restrict__ bars0,
    const float* __restrict__ bars1,
    const float* __restrict__ pts,
    float* __restrict__ out)
{
    const size_t GM0 = 2ull * PP * RR;                     // 25000
    const size_t GC0 = GM0 + (size_t)RR * PP * 2 * SS;     // 50025000
    const size_t GM1 = GC0 + (size_t)RR * PP * 2;          // 50050000
    const size_t GC1 = GM1 + (size_t)RR * PP * 2 * SS;     // 100050000

    int p = blockIdx.x;
    int t = threadIdx.x;
    int warp = t >> 5, lane = t & 31;

    __shared__ float    sscale[10];
    __shared__ unsigned sflags[10];

    float2 pt = ((const float2*)pts)[p];
    float ptx = pt.x, pty = pt.y;
    float psum = __fadd_rn(ptx, pty);

    if (t < 10) {
        int h = t / RR, r = t % RR;
        float bar = (h ? bars1 : bars0)[p * RR + r];
        out[(size_t)h * PP * RR + (size_t)p * RR + r] = bar;   // bars_stack output
        sscale[t] = __fadd_rn(bar, 0.01f);                     // scale = bar + GRID_RES
        sflags[t] = 0u;
    }
    __syncthreads();

    for (int c = 0; c < 10; ++c) {
        float  sc = sscale[c];
        size_t rowbase = (c < RR ? GM0 : GM1) +
                         ((size_t)(c % RR) * PP + p) * (size_t)(2 * SS);

        // ---- Phase 1: stream-zero the 16KB row (float4 stores) ----
        float4* row4 = (float4*)(out + rowbase);
        #pragma unroll
        for (int i = 0; i < 4; ++i) {
            int idx = t + i * 256;
            if (idx < SS / 2) row4[idx] = make_float4(0.f, 0.f, 0.f, 0.f);
        }
        __syncthreads();   // order zero -> sparse overwrite (row is L2-hot)

        // ---- Phase 2: sparse overwrite of nonzeros ----
        // 10 ranges: axis in {x,y} x shift k in {-2..2}; spread over 8 warps
        for (int rid = warp; rid < 10; rid += 8) {
            int   axis = rid / 5;
            float kf   = (float)(rid % 5 - 2);
            float myp  = axis ? pty : ptx;       // line anchor for this axis
            float otp  = axis ? ptx : pty;       // companion axis anchor
            // Exact reference arithmetic (mul then add, no FMA fusion):
            float line  = __fadd_rn(__fmul_rn(kf, sc), myp);
            float lastc = __fadd_rn(__fmul_rn(2.0f, sc), otp); // last_{other axis}
            // Widened bucket range (max tol = 0.01001 < 0.0101)
            int b0 = min(NB - 1, max(0, (int)floorf((line - 0.0101f) * (float)NB)));
            int b1 = min(NB - 1, max(0, (int)floorf((line + 0.0101f) * (float)NB)));
            const int*   offs = axis ? g_ofy : g_ofx;
            const float* keys = axis ? g_ky  : g_kx;
            const float* comp = axis ? g_cy  : g_cx;
            const int*   sarr = axis ? g_sy  : g_sx;
            int lo = __ldg(&offs[b0]);
            int hi = __ldg(&offs[b1 + 1]);
            for (int i = lo + lane; i < hi; i += 32) {
                float key = __ldg(&keys[i]);                       // f_axis[s]
                float tol = __fadd_rn(0.01f, __fmul_rn(1e-5f, fabsf(key)));
                if (fabsf(__fadd_rn(line, -key)) > tol) continue;  // close?
                float other = __ldg(&comp[i]);                     // f_other[s]
                if (!(other <= lastc)) continue;                   // cond gate
                float fsum = __fadd_rn(key, other);                // fx+fy (commutes)
                if (fsum == psum) continue;                        // value 0
                bool above = fsum > psum;
                int s = __ldg(&sarr[i]);
                out[rowbase + 2 * (size_t)s + (size_t)axis] = above ? 1.0f : -1.0f;
                unsigned bits = (axis ? 4u : 1u) << (above ? 0 : 1);
                atomicOr(&sflags[c], bits);
            }
        }
        // No sync needed here: next combo's zero phase targets a different row,
        // and its own __syncthreads orders everything.
    }
    __syncthreads();

    if (t < 10) {
        unsigned fl = sflags[t];
        // cx = anyUpper ? -1 : anyLower ? 1 : 0   (signs flipped vs gm)
        float cxv = (fl & 1u) ? -1.0f : ((fl & 2u) ? 1.0f : 0.0f);
        float cyv = (fl & 4u) ? -1.0f : ((fl & 8u) ? 1.0f : 0.0f);
        size_t gcb = (t < RR ? GC0 : GC1) + ((size_t)(t % RR) * PP + p) * 2;
        out[gcb]     = cxv;
        out[gcb + 1] = cyv;
    }
}

extern "C" void kernel_launch(void* const* d_in, const int* in_sizes, int n_in,
                              void* d_out, int out_size)
{
    (void)in_sizes; (void)n_in; (void)out_size;
    const float* filtration = (const float*)d_in[0];   // (S,2)
    const float* bars0      = (const float*)d_in[1];   // (P,R)
    const float* bars1      = (const float*)d_in[2];   // (P,R)
    const float* pts        = (const float*)d_in[3];   // (P,2)
    float* out = (float*)d_out;

    bin_kernel<<<1, 256>>>(filtration);
    grad_kernel<<<PP, 256>>>(bars0, bars1, pts, out);
}